// round 15
// baseline (speedup 1.0000x reference)
#include <cuda_runtime.h>
#include <math.h>

// ---------------------------------------------------------------------------
// att_lstm round 15: round-14 champion + the 16-step LSTM recurrence fused
// into ONE persistent kernel (256 co-resident CTAs, generation-counter grid
// barriers). GEMM mainloop + cell math byte-identical to champion.
// Host-side SM-count guard falls back to per-step launches if co-residency
// cannot be guaranteed.
// ---------------------------------------------------------------------------

#define B_    2048
#define SEQ_  16
#define DIM_  1024
#define HID_  512
#define DK_   512
#define NH_   4
#define DH_   128
#define G4_   (4 * HID_)      // 2048
#define BS_   (B_ * SEQ_)     // 32768
#define EPS_  1e-5f

#define MT 128
#define NT 128
#define BK 32
#define ASTR 36
#define ABYTES (128 * ASTR * 4)       // 18432
#define BBYTES (2 * 16 * 512)         // 16384
#define STG (ABYTES + BBYTES)         // 34816
#define NSTG 3
#define SMEM_G (NSTG * STG)           // 104448

// ------------------------------- scratch -----------------------------------
__device__ float d_mods [(long)BS_ * 4096];
__device__ float d_fusWp[4096 * DIM_];
__device__ float d_Wihp [G4_ * DIM_];
__device__ float d_Whhp [G4_ * HID_];
__device__ float d_wqp  [DK_ * HID_];
__device__ float d_wkp  [DK_ * HID_];
__device__ float d_wvp  [NH_ * DK_ * HID_];
__device__ float d_woutp[DK_ * NH_ * DK_];
__device__ float d_vt  [(long)BS_ * DIM_];
__device__ float d_gx  [(long)BS_ * G4_];
__device__ float d_hw  [B_  * G4_];
__device__ float d_h   [B_  * HID_];
__device__ float d_c   [B_  * HID_];
__device__ float d_lstm[(long)BS_ * HID_];
__device__ float d_kall[(long)BS_ * DK_];
__device__ float d_qb  [B_  * DK_];
__device__ float d_m   [B_  * NH_ * HID_];
__device__ float d_ctx [B_  * NH_ * DK_];
__device__ float d_oh  [B_  * DK_];
__device__ float d_diff[B_];
__device__ unsigned d_bar;            // zero-initialized grid-barrier counter

// --------------------------- helpers ---------------------------------------
__device__ __forceinline__ float sigm(float x) { return 1.0f / (1.0f + expf(-x)); }

__device__ __forceinline__ float f2tf(float f) {
    unsigned u;
    asm("cvt.rna.tf32.f32 %0, %1;" : "=r"(u) : "f"(f));
    return __uint_as_float(u);
}

__device__ __forceinline__ void cpa16(unsigned dst, const void* src) {
    asm volatile("cp.async.cg.shared.global [%0], [%1], 16;\n" :: "r"(dst), "l"(src));
}
__device__ __forceinline__ void cpa_commit() { asm volatile("cp.async.commit_group;\n"); }
__device__ __forceinline__ void cpa_wait1()  { asm volatile("cp.async.wait_group 1;\n"); }
__device__ __forceinline__ void cpa_wait0()  { asm volatile("cp.async.wait_group 0;\n"); }

__device__ __forceinline__ void ldm4(unsigned* r, unsigned addr) {
    asm volatile("ldmatrix.sync.aligned.m8n8.x4.shared.b16 {%0,%1,%2,%3}, [%4];"
        : "=r"(r[0]), "=r"(r[1]), "=r"(r[2]), "=r"(r[3]) : "r"(addr));
}

__device__ __forceinline__ void lds2(unsigned& a, unsigned& b, unsigned addr) {
    asm volatile("ld.shared.v2.b32 {%0,%1}, [%2];" : "=r"(a), "=r"(b) : "r"(addr));
}

__device__ __forceinline__ void mma_tf32(float* c, const unsigned* a,
                                         unsigned b0, unsigned b1) {
    asm volatile(
        "mma.sync.aligned.m16n8k8.row.col.f32.tf32.tf32.f32 "
        "{%0,%1,%2,%3},{%4,%5,%6,%7},{%8,%9},{%0,%1,%2,%3};\n"
        : "+f"(c[0]), "+f"(c[1]), "+f"(c[2]), "+f"(c[3])
        : "r"(a[0]), "r"(a[1]), "r"(a[2]), "r"(a[3]), "r"(b0), "r"(b1));
}

__device__ __forceinline__ float2 blockReduce2(float a, float b) {
    __shared__ float s1[8], s2[8];
    const unsigned m = 0xffffffffu;
    #pragma unroll
    for (int o = 16; o > 0; o >>= 1) {
        a += __shfl_down_sync(m, a, o);
        b += __shfl_down_sync(m, b, o);
    }
    int w = threadIdx.x >> 5, l = threadIdx.x & 31;
    if (l == 0) { s1[w] = a; s2[w] = b; }
    __syncthreads();
    int nw = blockDim.x >> 5;
    if (w == 0) {
        a = (l < nw) ? s1[l] : 0.0f;
        b = (l < nw) ? s2[l] : 0.0f;
        #pragma unroll
        for (int o = 4; o > 0; o >>= 1) {
            a += __shfl_down_sync(m, a, o);
            b += __shfl_down_sync(m, b, o);
        }
        if (l == 0) { s1[0] = a; s2[0] = b; }
    }
    __syncthreads();
    float2 r = make_float2(s1[0], s2[0]);
    __syncthreads();
    return r;
}

// generation-counter grid barrier; exactly NBAR arrivals per episode.
__device__ __forceinline__ void grid_barrier256() {
    __syncthreads();
    __threadfence();
    if (threadIdx.x == 0) {
        unsigned old = atomicAdd(&d_bar, 1u);
        unsigned target = (old / 256u + 1u) * 256u;
        while (atomicAdd(&d_bar, 0u) < target) { }
        __threadfence();
    }
    __syncthreads();
}

// ------------------------ producers ----------------------------------------
__global__ void __launch_bounds__(256)
conv_concat(const float* __restrict__ p0, const float* __restrict__ p1,
            const float* __restrict__ p2, const float* __restrict__ p3,
            float* __restrict__ outp)
{
    long i = ((long)blockIdx.x * 256 + threadIdx.x) * 4;
    long n = (long)BS_ * 4096;
    if (i >= n) return;
    long r = i >> 12;
    int  c = (int)(i & 4095);
    int seg = c >> 10, cl = c & 1023;
    const float* p = (seg == 0) ? p0 : (seg == 1) ? p1 : (seg == 2) ? p2 : p3;
    float4 v = *(const float4*)(p + r * DIM_ + cl);
    v.x = f2tf(v.x); v.y = f2tf(v.y); v.z = f2tf(v.z); v.w = f2tf(v.w);
    *(float4*)(outp + i) = v;
}

#define SZ_FUS ((long)DIM_ * 4096)
#define SZ_IH  ((long)G4_ * DIM_)
#define SZ_HH  ((long)G4_ * HID_)
#define SZ_QK  ((long)DK_ * HID_)
#define SZ_WV  ((long)NH_ * DK_ * HID_)
#define SZ_OUT ((long)DK_ * NH_ * DK_)
__global__ void __launch_bounds__(256)
perm_all(const float* __restrict__ fus_W, const float* __restrict__ W_ih,
         const float* __restrict__ W_hh,  const float* __restrict__ wq_W,
         const float* __restrict__ wk_W,  const float* __restrict__ wv_W,
         const float* __restrict__ wout_W,
         float* __restrict__ fusWp, float* __restrict__ Wihp,
         float* __restrict__ Whhp,  float* __restrict__ wqp,
         float* __restrict__ wkp,   float* __restrict__ wvp,
         float* __restrict__ woutp)
{
    long i = (long)blockIdx.x * 256 + threadIdx.x;
    const long e0 = SZ_FUS, e1 = e0 + SZ_IH, e2 = e1 + SZ_HH, e3 = e2 + SZ_QK,
               e4 = e3 + SZ_QK, e5 = e4 + SZ_WV, e6 = e5 + SZ_OUT;
    if (i >= e6) return;
    const float* W; float* P; int N, K; long off;
    if (i < e0)      { W = fus_W;  P = fusWp;  N = DIM_; K = 4096;      off = i; }
    else if (i < e1) { W = W_ih;   P = Wihp;   N = G4_;  K = DIM_;      off = i - e0; }
    else if (i < e2) { W = W_hh;   P = Whhp;   N = G4_;  K = HID_;      off = i - e1; }
    else if (i < e3) { W = wq_W;   P = wqp;    N = DK_;  K = HID_;      off = i - e2; }
    else if (i < e4) { W = wk_W;   P = wkp;    N = DK_;  K = HID_;      off = i - e3; }
    else if (i < e5) {
        long o = i - e4;
        long hsz = (long)DK_ * HID_;
        int z = (int)(o / hsz);
        W = wv_W + (long)z * hsz; P = wvp + (long)z * hsz;
        N = DK_; K = HID_; off = o - (long)z * hsz;
    }
    else             { W = wout_W; P = woutp;  N = DK_;  K = NH_ * DK_; off = i - e5; }
    int k = (int)(off % K);
    int nn = (int)(off / K);
    int kg = k >> 4, nt = nn >> 3;
    int q2 = (k >> 3) & 1, pos = (k >> 2) & 1;
    int l = (nn & 7) * 4 + (k & 3);
    long o2 = ((((long)kg * (N >> 3) + nt) * 2 + q2) * 64) + l * 2 + pos;
    P[o2] = f2tf(W[off]);
}

__global__ void __launch_bounds__(256)
round_vec(const float* __restrict__ s, float* __restrict__ d, long n)
{
    long i = (long)blockIdx.x * 256 + threadIdx.x;
    if (i < n) d[i] = f2tf(s[i]);
}

// --------------------------- tf32 GEMM (champion) ----------------------------
__global__ void __launch_bounds__(256, 2)
tgemm(const float* __restrict__ A, int lda, long sAz,
      const float* __restrict__ Bp, long sBz, int N,
      float* __restrict__ C, int ldc, long sCz, int K,
      const float* __restrict__ bias, int sbz, int act, int rnd)
{
    extern __shared__ __align__(16) float dsm[];
    const int tid = threadIdx.x;
    const int m0 = blockIdx.y * MT;
    const int nt0 = blockIdx.x * 16;
    A  += (long)blockIdx.z * sAz;
    Bp += (long)blockIdx.z * sBz;
    C  += (long)blockIdx.z * sCz;
    const float* bz = bias ? bias + (long)blockIdx.z * sbz : (const float*)0;

    const int w = tid >> 5, lane = tid & 31;
    const int wm = w & 3, wn = w >> 2;
    const int gid = lane >> 2, tig = lane & 3;

    const unsigned sb = (unsigned)__cvta_generic_to_shared(dsm);
    const int NT8 = N >> 3;

    float acc[2][8][4];
    #pragma unroll
    for (int i = 0; i < 2; i++)
        #pragma unroll
        for (int j = 0; j < 8; j++)
            #pragma unroll
            for (int q = 0; q < 4; q++) acc[i][j][q] = 0.0f;

    const int KT = K / BK;

    const int ar = tid >> 3, ach = tid & 7;
    auto loadStage = [&](int stg, int k0) {
        const unsigned as = sb + (unsigned)stg * STG;
        #pragma unroll
        for (int i = 0; i < 4; i++) {
            int r = ar + i * 32;
            cpa16(as + (unsigned)(r * ASTR * 4 + ach * 16),
                  A + (long)(m0 + r) * lda + k0 + ach * 4);
        }
        const unsigned bs = as + ABYTES;
        const int kg0 = k0 >> 4;
        #pragma unroll
        for (int i = 0; i < 4; i++) {
            int g = i * 256 + tid;
            int kg2 = g >> 9, rest = g & 511;
            cpa16(bs + (unsigned)(kg2 * 8192 + rest * 16),
                  Bp + ((long)(kg0 + kg2) * NT8 + nt0) * 128 + rest * 4);
        }
    };

    loadStage(0, 0);
    cpa_commit();
    if (KT > 1) loadStage(1, BK);
    cpa_commit();

    const unsigned aoffL = (unsigned)((wm * 32 + (lane & 15)) * ASTR * 4 + (lane >> 4) * 16);
    const unsigned boffL = (unsigned)((wn * 8) * 512 + lane * 8);

    int stage = 0;
    for (int t = 0; t < KT; t++) {
        cpa_wait1();
        __syncthreads();
        const unsigned as = sb + (unsigned)stage * STG;
        const unsigned bs = as + ABYTES;
        #pragma unroll
        for (int kk = 0; kk < 4; kk++) {
            unsigned af0[4], af1[4];
            ldm4(af0, as + aoffL + kk * 32);
            ldm4(af1, as + aoffL + 16 * ASTR * 4 + kk * 32);
            const unsigned bb = bs + boffL + (kk >> 1) * 8192 + (kk & 1) * 256;
            #pragma unroll
            for (int j = 0; j < 8; j++) {
                unsigned b0, b1;
                lds2(b0, b1, bb + j * 512);
                mma_tf32(acc[0][j], af0, b0, b1);
                mma_tf32(acc[1][j], af1, b0, b1);
            }
        }
        if (t + 2 < KT) {
            int ns = stage + 2; if (ns >= NSTG) ns -= NSTG;
            loadStage(ns, (t + 2) * BK);
        }
        cpa_commit();
        if (++stage == NSTG) stage = 0;
    }

    const int n0 = nt0 * 8;
    #pragma unroll
    for (int i = 0; i < 2; i++) {
        const int r0 = m0 + wm * 32 + i * 16 + gid;
        #pragma unroll
        for (int j = 0; j < 8; j++) {
            const int col = n0 + wn * 64 + j * 8 + 2 * tig;
            float bx = 0.0f, by = 0.0f;
            if (bz) { bx = bz[col]; by = bz[col + 1]; }
            float v0x = acc[i][j][0] + bx, v0y = acc[i][j][1] + by;
            float v1x = acc[i][j][2] + bx, v1y = acc[i][j][3] + by;
            if (act) {
                v0x = fmaxf(v0x, 0.0f); v0y = fmaxf(v0y, 0.0f);
                v1x = fmaxf(v1x, 0.0f); v1y = fmaxf(v1y, 0.0f);
            }
            if (rnd) {
                v0x = f2tf(v0x); v0y = f2tf(v0y);
                v1x = f2tf(v1x); v1y = f2tf(v1y);
            }
            *(float2*)(C + (long)r0 * ldc + col) = make_float2(v0x, v0y);
            *(float2*)(C + (long)(r0 + 8) * ldc + col) = make_float2(v1x, v1y);
        }
    }
}

// --------------------- LSTM cell body (shared by both paths) ----------------
__device__ __forceinline__ void cell_row(
    float* sg, int b, int t,
    const float* __restrict__ hw, const float* __restrict__ gx,
    const float* __restrict__ g_hh, const float* __restrict__ b_hh,
    const float* __restrict__ g_c,  const float* __restrict__ b_c,
    float* __restrict__ h, float* __restrict__ c, float* __restrict__ lstm)
{
    const int tid = threadIdx.x;
    const float* row = hw + (long)b * G4_;
    float s = 0.0f, ss = 0.0f;
    for (int j = tid; j < G4_; j += 256) {
        float v = row[j];
        sg[j] = v; s += v; ss += v * v;
    }
    float2 r = blockReduce2(s, ss);
    float mean = r.x * (1.0f / G4_);
    float var  = r.y * (1.0f / G4_) - mean * mean;
    float inv  = rsqrtf(var + EPS_);

    const float* gxr = gx + ((long)b * SEQ_ + t) * G4_;
    float cval[2];
    float sc = 0.0f, ssc = 0.0f;
    #pragma unroll
    for (int rr = 0; rr < 2; rr++) {
        int j = rr * 256 + tid;
        float gi = (sg[j]        - mean) * inv * g_hh[j]        + b_hh[j]        + gxr[j];
        float gf = (sg[512 + j]  - mean) * inv * g_hh[512 + j]  + b_hh[512 + j]  + gxr[512 + j];
        float gg = (sg[1024 + j] - mean) * inv * g_hh[1024 + j] + b_hh[1024 + j] + gxr[1024 + j];
        float cn = sigm(gf) * c[(long)b * HID_ + j] + sigm(gi) * tanhf(gg);
        cval[rr] = cn;
        c[(long)b * HID_ + j] = cn;
        sc += cn; ssc += cn * cn;
    }
    float2 rc = blockReduce2(sc, ssc);
    float meanc = rc.x * (1.0f / HID_);
    float varc  = rc.y * (1.0f / HID_) - meanc * meanc;
    float invc  = rsqrtf(varc + EPS_);
    #pragma unroll
    for (int rr = 0; rr < 2; rr++) {
        int j = rr * 256 + tid;
        float go = (sg[1536 + j] - mean) * inv * g_hh[1536 + j] + b_hh[1536 + j] + gxr[1536 + j];
        float hn = sigm(go) * tanhf((cval[rr] - meanc) * invc * g_c[j] + b_c[j]);
        hn = f2tf(hn);
        h[(long)b * HID_ + j] = hn;
        lstm[((long)b * SEQ_ + t) * HID_ + j] = hn;
    }
}

// --------------------- persistent fused LSTM --------------------------------
// grid (16,16) = 256 CTAs, all co-resident. Per step: GEMM phase (own 128x128
// tile of hw = h @ Whh^T) -> grid barrier -> cell phase (8 batch rows/CTA)
// -> grid barrier. Math identical to per-step path.
__global__ void __launch_bounds__(256, 2)
lstm_persistent(const float* __restrict__ Bp,   // Whhp
                float* __restrict__ hw,
                float* __restrict__ h, float* __restrict__ c,
                const float* __restrict__ gx, float* __restrict__ lstm,
                const float* __restrict__ g_hh, const float* __restrict__ b_hh,
                const float* __restrict__ g_c,  const float* __restrict__ b_c)
{
    extern __shared__ __align__(16) float dsm[];
    const int tid = threadIdx.x;
    const int m0 = blockIdx.y * MT;
    const int nt0 = blockIdx.x * 16;
    const int N = G4_, K = HID_, lda = HID_, ldc = G4_;

    const int w = tid >> 5, lane = tid & 31;
    const int wm = w & 3, wn = w >> 2;
    const int gid = lane >> 2, tig = lane & 3;
    const unsigned sb = (unsigned)__cvta_generic_to_shared(dsm);
    const int NT8 = N >> 3;
    const int KT = K / BK;                       // 16
    const int ar = tid >> 3, ach = tid & 7;
    const unsigned aoffL = (unsigned)((wm * 32 + (lane & 15)) * ASTR * 4 + (lane >> 4) * 16);
    const unsigned boffL = (unsigned)((wn * 8) * 512 + lane * 8);
    const int zc = blockIdx.y * 16 + blockIdx.x; // 0..255 -> 8 cell rows

    for (int t = 0; t < SEQ_; t++) {
        // ---- GEMM phase: hw = h @ Whh^T (tile) ----
        float acc[2][8][4];
        #pragma unroll
        for (int i = 0; i < 2; i++)
            #pragma unroll
            for (int j = 0; j < 8; j++)
                #pragma unroll
                for (int q = 0; q < 4; q++) acc[i][j][q] = 0.0f;

        auto loadStage = [&](int stg, int k0) {
            const unsigned as = sb + (unsigned)stg * STG;
            #pragma unroll
            for (int i = 0; i < 4; i++) {
                int r = ar + i * 32;
                cpa16(as + (unsigned)(r * ASTR * 4 + ach * 16),
                      h + (long)(m0 + r) * lda + k0 + ach * 4);
            }
            const unsigned bs = as + ABYTES;
            const int kg0 = k0 >> 4;
            #pragma unroll
            for (int i = 0; i < 4; i++) {
                int g = i * 256 + tid;
                int kg2 = g >> 9, rest = g & 511;
                cpa16(bs + (unsigned)(kg2 * 8192 + rest * 16),
                      Bp + ((long)(kg0 + kg2) * NT8 + nt0) * 128 + rest * 4);
            }
        };

        loadStage(0, 0);
        cpa_commit();
        loadStage(1, BK);
        cpa_commit();

        int stage = 0;
        for (int kt = 0; kt < KT; kt++) {
            cpa_wait1();
            __syncthreads();
            const unsigned as = sb + (unsigned)stage * STG;
            const unsigned bs = as + ABYTES;
            #pragma unroll
            for (int kk = 0; kk < 4; kk++) {
                unsigned af0[4], af1[4];
                ldm4(af0, as + aoffL + kk * 32);
                ldm4(af1, as + aoffL + 16 * ASTR * 4 + kk * 32);
                const unsigned bb = bs + boffL + (kk >> 1) * 8192 + (kk & 1) * 256;
                #pragma unroll
                for (int j = 0; j < 8; j++) {
                    unsigned b0, b1;
                    lds2(b0, b1, bb + j * 512);
                    mma_tf32(acc[0][j], af0, b0, b1);
                    mma_tf32(acc[1][j], af1, b0, b1);
                }
            }
            if (kt + 2 < KT) {
                int ns = stage + 2; if (ns >= NSTG) ns -= NSTG;
                loadStage(ns, (kt + 2) * BK);
            }
            cpa_commit();
            if (++stage == NSTG) stage = 0;
        }
        cpa_wait0();     // drain empty groups before smem reuse next phase

        const int n0 = nt0 * 8;
        #pragma unroll
        for (int i = 0; i < 2; i++) {
            const int r0 = m0 + wm * 32 + i * 16 + gid;
            #pragma unroll
            for (int j = 0; j < 8; j++) {
                const int col = n0 + wn * 64 + j * 8 + 2 * tig;
                *(float2*)(hw + (long)r0 * ldc + col) =
                    make_float2(acc[i][j][0], acc[i][j][1]);
                *(float2*)(hw + (long)(r0 + 8) * ldc + col) =
                    make_float2(acc[i][j][2], acc[i][j][3]);
            }
        }

        grid_barrier256();

        // ---- cell phase: 8 batch rows per CTA ----
        for (int rrow = 0; rrow < 8; rrow++) {
            int b = zc * 8 + rrow;
            cell_row(dsm, b, t, hw, gx, g_hh, b_hh, g_c, b_c, h, c, lstm);
        }

        grid_barrier256();
    }
}

// --------------------- pointwise kernels ------------------------------------
__global__ void __launch_bounds__(256)
ln_rows_kernel(float* __restrict__ x, const float* __restrict__ g,
               const float* __restrict__ b)
{
    __shared__ float sx[G4_];
    long base = (long)blockIdx.x * G4_;
    float s = 0.0f, ss = 0.0f;
    for (int j = threadIdx.x; j < G4_; j += 256) {
        float v = x[base + j];
        sx[j] = v; s += v; ss += v * v;
    }
    float2 r = blockReduce2(s, ss);
    float mean = r.x * (1.0f / G4_);
    float var  = r.y * (1.0f / G4_) - mean * mean;
    float inv  = rsqrtf(var + EPS_);
    for (int j = threadIdx.x; j < G4_; j += 256)
        x[base + j] = (sx[j] - mean) * inv * g[j] + b[j];
}

__global__ void __launch_bounds__(256)
lstm_cell_kernel(const float* __restrict__ hw,
                 const float* __restrict__ gx,
                 const float* __restrict__ g_hh, const float* __restrict__ b_hh,
                 const float* __restrict__ g_c,  const float* __restrict__ b_c,
                 float* __restrict__ h, float* __restrict__ c,
                 float* __restrict__ lstm, int t)
{
    __shared__ float sg[G4_];
    cell_row(sg, blockIdx.x, t, hw, gx, g_hh, b_hh, g_c, b_c, h, c, lstm);
}

__global__ void __launch_bounds__(128)
attn_kernel(const float* __restrict__ kall, const float* __restrict__ qb,
            const float* __restrict__ lstm, float* __restrict__ mbuf)
{
    const int hidx = blockIdx.x;
    const int b    = blockIdx.y;
    const int tid  = threadIdx.x;
    __shared__ float ssc[SEQ_];
    __shared__ float wsum[SEQ_][4];

    float qv = qb[(long)b * DK_ + hidx * DH_ + tid];
    int w = tid >> 5, l = tid & 31;
    for (int s = 0; s < SEQ_; s++) {
        float v = kall[((long)b * SEQ_ + s) * DK_ + hidx * DH_ + tid] * qv;
        #pragma unroll
        for (int o = 16; o > 0; o >>= 1) v += __shfl_down_sync(0xffffffffu, v, o);
        if (l == 0) wsum[s][w] = v;
    }
    __syncthreads();
    if (tid < SEQ_) {
        float sc = wsum[tid][0] + wsum[tid][1] + wsum[tid][2] + wsum[tid][3];
        ssc[tid] = sc * 0.08838834764831845f;
    }
    __syncthreads();

    float e[SEQ_];
    float mx = -1e30f;
    #pragma unroll
    for (int s = 0; s < SEQ_; s++) mx = fmaxf(mx, ssc[s]);
    float den = 0.0f;
    #pragma unroll
    for (int s = 0; s < SEQ_; s++) { e[s] = expf(ssc[s] - mx); den += e[s]; }
    float dinv = 1.0f / den;

    #pragma unroll
    for (int rr = 0; rr < HID_ / 128; rr++) {
        int d = rr * 128 + tid;
        float acc = 0.0f;
        #pragma unroll
        for (int s = 0; s < SEQ_; s++)
            acc += e[s] * lstm[((long)b * SEQ_ + s) * HID_ + d];
        mbuf[((long)b * NH_ + hidx) * HID_ + d] = f2tf(acc * dinv);
    }
}

__global__ void __launch_bounds__(256)
out_final_kernel(const float* __restrict__ oh, const float* __restrict__ outW,
                 const float* __restrict__ outb, const float* __restrict__ label,
                 float* __restrict__ out, float* __restrict__ diff)
{
    int w = threadIdx.x >> 5, l = threadIdx.x & 31;
    int b = blockIdx.x * 8 + w;
    float s = 0.0f;
    for (int j = l; j < DK_; j += 32) s += oh[(long)b * DK_ + j] * outW[j];
    #pragma unroll
    for (int o = 16; o > 0; o >>= 1) s += __shfl_down_sync(0xffffffffu, s, o);
    if (l == 0) {
        float v = s + outb[0];
        out[1 + b] = v;
        float d = v - label[(long)b * SEQ_ + (SEQ_ - 1)];
        diff[b] = d * d;
    }
}

__global__ void __launch_bounds__(256)
loss_kernel(const float* __restrict__ diff, float* __restrict__ out)
{
    float s = 0.0f;
    for (int j = threadIdx.x; j < B_; j += 256) s += diff[j];
    float2 r = blockReduce2(s, 0.0f);
    if (threadIdx.x == 0) out[0] = r.x * (1.0f / B_);
}

// ------------------------------- launch -------------------------------------
static inline void getp(void** p, const void* sym) { cudaGetSymbolAddress(p, sym); }

extern "C" void kernel_launch(void* const* d_in, const int* in_sizes, int n_in,
                              void* d_out, int out_size)
{
    const float* visual = (const float*)d_in[0];
    const float* text   = (const float*)d_in[1];
    const float* user   = (const float*)d_in[2];
    const float* cat    = (const float*)d_in[3];
    const float* label  = (const float*)d_in[4];
    const float* h0     = (const float*)d_in[5];
    const float* c0     = (const float*)d_in[6];
    const float* fus_W  = (const float*)d_in[7];
    const float* fus_b  = (const float*)d_in[8];
    const float* W_ih   = (const float*)d_in[9];
    const float* W_hh   = (const float*)d_in[10];
    const float* g_ih   = (const float*)d_in[11];
    const float* b_ih   = (const float*)d_in[12];
    const float* g_hh   = (const float*)d_in[13];
    const float* b_hh   = (const float*)d_in[14];
    const float* g_c    = (const float*)d_in[15];
    const float* b_c    = (const float*)d_in[16];
    const float* wq_W   = (const float*)d_in[17];
    const float* wq_b   = (const float*)d_in[18];
    const float* wk_W   = (const float*)d_in[19];
    const float* wk_b   = (const float*)d_in[20];
    const float* wv_W   = (const float*)d_in[21];
    const float* wv_b   = (const float*)d_in[22];
    const float* wout_W = (const float*)d_in[23];
    const float* wout_b = (const float*)d_in[24];
    const float* out_W  = (const float*)d_in[25];
    const float* out_b  = (const float*)d_in[26];
    float* out = (float*)d_out;

    float *mods, *fusWp, *Wihp, *Whhp, *wqp, *wkp, *wvp, *woutp;
    float *vt, *gx, *hw, *h, *c, *lstm, *kall, *qb, *m, *ctx, *oh, *diff;
    getp((void**)&mods,  d_mods);  getp((void**)&fusWp, d_fusWp);
    getp((void**)&Wihp,  d_Wihp);  getp((void**)&Whhp,  d_Whhp);
    getp((void**)&wqp,   d_wqp);   getp((void**)&wkp,   d_wkp);
    getp((void**)&wvp,   d_wvp);   getp((void**)&woutp, d_woutp);
    getp((void**)&vt,    d_vt);    getp((void**)&gx,    d_gx);
    getp((void**)&hw,    d_hw);    getp((void**)&h,     d_h);
    getp((void**)&c,     d_c);     getp((void**)&lstm,  d_lstm);
    getp((void**)&kall,  d_kall);  getp((void**)&qb,    d_qb);
    getp((void**)&m,     d_m);     getp((void**)&ctx,   d_ctx);
    getp((void**)&oh,    d_oh);    getp((void**)&diff,  d_diff);

    cudaFuncSetAttribute(tgemm, cudaFuncAttributeMaxDynamicSharedMemorySize, SMEM_G);
    cudaFuncSetAttribute(lstm_persistent, cudaFuncAttributeMaxDynamicSharedMemorySize, SMEM_G);

    // co-residency guard for the persistent path
    int sms = 0;
    cudaDeviceGetAttribute(&sms, cudaDevAttrMultiProcessorCount, 0);
    const bool persistent_ok = (2 * sms >= 256);

    // 0. producers
    {
        long nthr = (long)BS_ * 4096 / 4;
        conv_concat<<<(unsigned)((nthr + 255) / 256), 256>>>(visual, text, user, cat, mods);
    }
    {
        long total = SZ_FUS + SZ_IH + SZ_HH + 2 * SZ_QK + SZ_WV + SZ_OUT;
        perm_all<<<(unsigned)((total + 255) / 256), 256>>>(
            fus_W, W_ih, W_hh, wq_W, wk_W, wv_W, wout_W,
            fusWp, Wihp, Whhp, wqp, wkp, wvp, woutp);
    }
    round_vec<<<(B_ * HID_ + 255) / 256, 256>>>(h0, h, (long)B_ * HID_);
    cudaMemcpyAsync(c, c0, (size_t)B_ * HID_ * sizeof(float), cudaMemcpyDeviceToDevice, 0);

    // 1. fusion GEMM + relu -> vt (rounded)
    tgemm<<<dim3(DIM_ / NT, BS_ / MT), 256, SMEM_G>>>(
        mods, 4096, 0, fusWp, 0, DIM_, vt, DIM_, 0, 4096, fus_b, 0, 1, 1);

    // 2. gx = vt @ W_ih^T, then LN
    tgemm<<<dim3(G4_ / NT, BS_ / MT), 256, SMEM_G>>>(
        vt, DIM_, 0, Wihp, 0, G4_, gx, G4_, 0, DIM_, (const float*)0, 0, 0, 0);
    ln_rows_kernel<<<BS_, 256>>>(gx, g_ih, b_ih);

    // 3. LSTM recurrence
    if (persistent_ok) {
        lstm_persistent<<<dim3(16, 16), 256, SMEM_G>>>(
            Whhp, hw, h, c, gx, lstm, g_hh, b_hh, g_c, b_c);
    } else {
        for (int t = 0; t < SEQ_; t++) {
            tgemm<<<dim3(G4_ / NT, B_ / MT), 256, SMEM_G>>>(
                h, HID_, 0, Whhp, 0, G4_, hw, G4_, 0, HID_, (const float*)0, 0, 0, 0);
            lstm_cell_kernel<<<B_, 256>>>(hw, gx, g_hh, b_hh, g_c, b_c, h, c, lstm, t);
        }
    }

    // 4. k / q projections
    tgemm<<<dim3(DK_ / NT, BS_ / MT), 256, SMEM_G>>>(
        lstm, HID_, 0, wkp, 0, DK_, kall, DK_, 0, HID_, wk_b, 0, 0, 0);
    tgemm<<<dim3(DK_ / NT, B_ / MT), 256, SMEM_G>>>(
        h, HID_, 0, wqp, 0, DK_, qb, DK_, 0, HID_, wq_b, 0, 0, 0);

    // 5. attention -> m (rounded)
    attn_kernel<<<dim3(NH_, B_), 128>>>(kall, qb, lstm, m);

    // 6. ctx = wv_W . m  (batched over heads, rounded)
    tgemm<<<dim3(DK_ / NT, B_ / MT, NH_), 256, SMEM_G>>>(
        m, NH_ * HID_, HID_, wvp, (long)DK_ * HID_, DK_,
        ctx, NH_ * DK_, DK_, HID_, wv_b, DK_, 0, 1);

    // 7. out_h = ctx @ wout_W^T
    tgemm<<<dim3(DK_ / NT, B_ / MT), 256, SMEM_G>>>(
        ctx, NH_ * DK_, 0, woutp, 0, DK_, oh, DK_, 0, NH_ * DK_, wout_b, 0, 0, 0);

    // 8. final projection + loss
    out_final_kernel<<<B_ / 8, 256>>>(oh, out_W, out_b, label, out, diff);
    loss_kernel<<<1, 256>>>(diff, out);
}

// round 16
// speedup vs baseline: 1.1320x; 1.1320x over previous
#include <cuda_runtime.h>
#include <math.h>

// ---------------------------------------------------------------------------
// att_lstm round 16: round-14 champion (tf32 mma.sync GEMMs, per-step LSTM
// launches) + pointwise traffic fixes: attn one-block-per-batch (4x less lstm
// reads), ln_rows + cell row loads vectorized to LDG.128.
// ---------------------------------------------------------------------------

#define B_    2048
#define SEQ_  16
#define DIM_  1024
#define HID_  512
#define DK_   512
#define NH_   4
#define DH_   128
#define G4_   (4 * HID_)      // 2048
#define BS_   (B_ * SEQ_)     // 32768
#define EPS_  1e-5f

#define MT 128
#define NT 128
#define BK 32
#define ASTR 36
#define ABYTES (128 * ASTR * 4)       // 18432
#define BBYTES (2 * 16 * 512)         // 16384
#define STG (ABYTES + BBYTES)         // 34816
#define NSTG 3
#define SMEM_G (NSTG * STG)           // 104448

// ------------------------------- scratch -----------------------------------
__device__ float d_mods [(long)BS_ * 4096];
__device__ float d_fusWp[4096 * DIM_];
__device__ float d_Wihp [G4_ * DIM_];
__device__ float d_Whhp [G4_ * HID_];
__device__ float d_wqp  [DK_ * HID_];
__device__ float d_wkp  [DK_ * HID_];
__device__ float d_wvp  [NH_ * DK_ * HID_];
__device__ float d_woutp[DK_ * NH_ * DK_];
__device__ float d_vt  [(long)BS_ * DIM_];
__device__ float d_gx  [(long)BS_ * G4_];
__device__ float d_hw  [B_  * G4_];
__device__ float d_h   [B_  * HID_];
__device__ float d_c   [B_  * HID_];
__device__ float d_lstm[(long)BS_ * HID_];
__device__ float d_kall[(long)BS_ * DK_];
__device__ float d_qb  [B_  * DK_];
__device__ float d_m   [B_  * NH_ * HID_];
__device__ float d_ctx [B_  * NH_ * DK_];
__device__ float d_oh  [B_  * DK_];
__device__ float d_diff[B_];

// --------------------------- helpers ---------------------------------------
__device__ __forceinline__ float sigm(float x) { return 1.0f / (1.0f + expf(-x)); }

__device__ __forceinline__ float f2tf(float f) {
    unsigned u;
    asm("cvt.rna.tf32.f32 %0, %1;" : "=r"(u) : "f"(f));
    return __uint_as_float(u);
}

__device__ __forceinline__ void cpa16(unsigned dst, const void* src) {
    asm volatile("cp.async.cg.shared.global [%0], [%1], 16;\n" :: "r"(dst), "l"(src));
}
__device__ __forceinline__ void cpa_commit() { asm volatile("cp.async.commit_group;\n"); }
__device__ __forceinline__ void cpa_wait1()  { asm volatile("cp.async.wait_group 1;\n"); }

__device__ __forceinline__ void ldm4(unsigned* r, unsigned addr) {
    asm volatile("ldmatrix.sync.aligned.m8n8.x4.shared.b16 {%0,%1,%2,%3}, [%4];"
        : "=r"(r[0]), "=r"(r[1]), "=r"(r[2]), "=r"(r[3]) : "r"(addr));
}

__device__ __forceinline__ void lds2(unsigned& a, unsigned& b, unsigned addr) {
    asm volatile("ld.shared.v2.b32 {%0,%1}, [%2];" : "=r"(a), "=r"(b) : "r"(addr));
}

__device__ __forceinline__ void mma_tf32(float* c, const unsigned* a,
                                         unsigned b0, unsigned b1) {
    asm volatile(
        "mma.sync.aligned.m16n8k8.row.col.f32.tf32.tf32.f32 "
        "{%0,%1,%2,%3},{%4,%5,%6,%7},{%8,%9},{%0,%1,%2,%3};\n"
        : "+f"(c[0]), "+f"(c[1]), "+f"(c[2]), "+f"(c[3])
        : "r"(a[0]), "r"(a[1]), "r"(a[2]), "r"(a[3]), "r"(b0), "r"(b1));
}

__device__ __forceinline__ float2 blockReduce2(float a, float b) {
    __shared__ float s1[8], s2[8];
    const unsigned m = 0xffffffffu;
    #pragma unroll
    for (int o = 16; o > 0; o >>= 1) {
        a += __shfl_down_sync(m, a, o);
        b += __shfl_down_sync(m, b, o);
    }
    int w = threadIdx.x >> 5, l = threadIdx.x & 31;
    if (l == 0) { s1[w] = a; s2[w] = b; }
    __syncthreads();
    int nw = blockDim.x >> 5;
    if (w == 0) {
        a = (l < nw) ? s1[l] : 0.0f;
        b = (l < nw) ? s2[l] : 0.0f;
        #pragma unroll
        for (int o = 4; o > 0; o >>= 1) {
            a += __shfl_down_sync(m, a, o);
            b += __shfl_down_sync(m, b, o);
        }
        if (l == 0) { s1[0] = a; s2[0] = b; }
    }
    __syncthreads();
    float2 r = make_float2(s1[0], s2[0]);
    __syncthreads();
    return r;
}

// ------------------------ producers ----------------------------------------
__global__ void __launch_bounds__(256)
conv_concat(const float* __restrict__ p0, const float* __restrict__ p1,
            const float* __restrict__ p2, const float* __restrict__ p3,
            float* __restrict__ outp)
{
    long i = ((long)blockIdx.x * 256 + threadIdx.x) * 4;
    long n = (long)BS_ * 4096;
    if (i >= n) return;
    long r = i >> 12;
    int  c = (int)(i & 4095);
    int seg = c >> 10, cl = c & 1023;
    const float* p = (seg == 0) ? p0 : (seg == 1) ? p1 : (seg == 2) ? p2 : p3;
    float4 v = *(const float4*)(p + r * DIM_ + cl);
    v.x = f2tf(v.x); v.y = f2tf(v.y); v.z = f2tf(v.z); v.w = f2tf(v.w);
    *(float4*)(outp + i) = v;
}

#define SZ_FUS ((long)DIM_ * 4096)
#define SZ_IH  ((long)G4_ * DIM_)
#define SZ_HH  ((long)G4_ * HID_)
#define SZ_QK  ((long)DK_ * HID_)
#define SZ_WV  ((long)NH_ * DK_ * HID_)
#define SZ_OUT ((long)DK_ * NH_ * DK_)
__global__ void __launch_bounds__(256)
perm_all(const float* __restrict__ fus_W, const float* __restrict__ W_ih,
         const float* __restrict__ W_hh,  const float* __restrict__ wq_W,
         const float* __restrict__ wk_W,  const float* __restrict__ wv_W,
         const float* __restrict__ wout_W,
         float* __restrict__ fusWp, float* __restrict__ Wihp,
         float* __restrict__ Whhp,  float* __restrict__ wqp,
         float* __restrict__ wkp,   float* __restrict__ wvp,
         float* __restrict__ woutp)
{
    long i = (long)blockIdx.x * 256 + threadIdx.x;
    const long e0 = SZ_FUS, e1 = e0 + SZ_IH, e2 = e1 + SZ_HH, e3 = e2 + SZ_QK,
               e4 = e3 + SZ_QK, e5 = e4 + SZ_WV, e6 = e5 + SZ_OUT;
    if (i >= e6) return;
    const float* W; float* P; int N, K; long off;
    if (i < e0)      { W = fus_W;  P = fusWp;  N = DIM_; K = 4096;      off = i; }
    else if (i < e1) { W = W_ih;   P = Wihp;   N = G4_;  K = DIM_;      off = i - e0; }
    else if (i < e2) { W = W_hh;   P = Whhp;   N = G4_;  K = HID_;      off = i - e1; }
    else if (i < e3) { W = wq_W;   P = wqp;    N = DK_;  K = HID_;      off = i - e2; }
    else if (i < e4) { W = wk_W;   P = wkp;    N = DK_;  K = HID_;      off = i - e3; }
    else if (i < e5) {
        long o = i - e4;
        long hsz = (long)DK_ * HID_;
        int z = (int)(o / hsz);
        W = wv_W + (long)z * hsz; P = wvp + (long)z * hsz;
        N = DK_; K = HID_; off = o - (long)z * hsz;
    }
    else             { W = wout_W; P = woutp;  N = DK_;  K = NH_ * DK_; off = i - e5; }
    int k = (int)(off % K);
    int nn = (int)(off / K);
    int kg = k >> 4, nt = nn >> 3;
    int q2 = (k >> 3) & 1, pos = (k >> 2) & 1;
    int l = (nn & 7) * 4 + (k & 3);
    long o2 = ((((long)kg * (N >> 3) + nt) * 2 + q2) * 64) + l * 2 + pos;
    P[o2] = f2tf(W[off]);
}

__global__ void __launch_bounds__(256)
round_vec(const float* __restrict__ s, float* __restrict__ d, long n)
{
    long i = (long)blockIdx.x * 256 + threadIdx.x;
    if (i < n) d[i] = f2tf(s[i]);
}

// --------------------------- tf32 GEMM (champion) ----------------------------
__global__ void __launch_bounds__(256, 2)
tgemm(const float* __restrict__ A, int lda, long sAz,
      const float* __restrict__ Bp, long sBz, int N,
      float* __restrict__ C, int ldc, long sCz, int K,
      const float* __restrict__ bias, int sbz, int act, int rnd)
{
    extern __shared__ __align__(16) float dsm[];
    const int tid = threadIdx.x;
    const int m0 = blockIdx.y * MT;
    const int nt0 = blockIdx.x * 16;
    A  += (long)blockIdx.z * sAz;
    Bp += (long)blockIdx.z * sBz;
    C  += (long)blockIdx.z * sCz;
    const float* bz = bias ? bias + (long)blockIdx.z * sbz : (const float*)0;

    const int w = tid >> 5, lane = tid & 31;
    const int wm = w & 3, wn = w >> 2;
    const int gid = lane >> 2, tig = lane & 3;

    const unsigned sb = (unsigned)__cvta_generic_to_shared(dsm);
    const int NT8 = N >> 3;

    float acc[2][8][4];
    #pragma unroll
    for (int i = 0; i < 2; i++)
        #pragma unroll
        for (int j = 0; j < 8; j++)
            #pragma unroll
            for (int q = 0; q < 4; q++) acc[i][j][q] = 0.0f;

    const int KT = K / BK;

    const int ar = tid >> 3, ach = tid & 7;
    auto loadStage = [&](int stg, int k0) {
        const unsigned as = sb + (unsigned)stg * STG;
        #pragma unroll
        for (int i = 0; i < 4; i++) {
            int r = ar + i * 32;
            cpa16(as + (unsigned)(r * ASTR * 4 + ach * 16),
                  A + (long)(m0 + r) * lda + k0 + ach * 4);
        }
        const unsigned bs = as + ABYTES;
        const int kg0 = k0 >> 4;
        #pragma unroll
        for (int i = 0; i < 4; i++) {
            int g = i * 256 + tid;
            int kg2 = g >> 9, rest = g & 511;
            cpa16(bs + (unsigned)(kg2 * 8192 + rest * 16),
                  Bp + ((long)(kg0 + kg2) * NT8 + nt0) * 128 + rest * 4);
        }
    };

    loadStage(0, 0);
    cpa_commit();
    if (KT > 1) loadStage(1, BK);
    cpa_commit();

    const unsigned aoffL = (unsigned)((wm * 32 + (lane & 15)) * ASTR * 4 + (lane >> 4) * 16);
    const unsigned boffL = (unsigned)((wn * 8) * 512 + lane * 8);

    int stage = 0;
    for (int t = 0; t < KT; t++) {
        cpa_wait1();
        __syncthreads();
        const unsigned as = sb + (unsigned)stage * STG;
        const unsigned bs = as + ABYTES;
        #pragma unroll
        for (int kk = 0; kk < 4; kk++) {
            unsigned af0[4], af1[4];
            ldm4(af0, as + aoffL + kk * 32);
            ldm4(af1, as + aoffL + 16 * ASTR * 4 + kk * 32);
            const unsigned bb = bs + boffL + (kk >> 1) * 8192 + (kk & 1) * 256;
            #pragma unroll
            for (int j = 0; j < 8; j++) {
                unsigned b0, b1;
                lds2(b0, b1, bb + j * 512);
                mma_tf32(acc[0][j], af0, b0, b1);
                mma_tf32(acc[1][j], af1, b0, b1);
            }
        }
        if (t + 2 < KT) {
            int ns = stage + 2; if (ns >= NSTG) ns -= NSTG;
            loadStage(ns, (t + 2) * BK);
        }
        cpa_commit();
        if (++stage == NSTG) stage = 0;
    }

    const int n0 = nt0 * 8;
    #pragma unroll
    for (int i = 0; i < 2; i++) {
        const int r0 = m0 + wm * 32 + i * 16 + gid;
        #pragma unroll
        for (int j = 0; j < 8; j++) {
            const int col = n0 + wn * 64 + j * 8 + 2 * tig;
            float bx = 0.0f, by = 0.0f;
            if (bz) { bx = bz[col]; by = bz[col + 1]; }
            float v0x = acc[i][j][0] + bx, v0y = acc[i][j][1] + by;
            float v1x = acc[i][j][2] + bx, v1y = acc[i][j][3] + by;
            if (act) {
                v0x = fmaxf(v0x, 0.0f); v0y = fmaxf(v0y, 0.0f);
                v1x = fmaxf(v1x, 0.0f); v1y = fmaxf(v1y, 0.0f);
            }
            if (rnd) {
                v0x = f2tf(v0x); v0y = f2tf(v0y);
                v1x = f2tf(v1x); v1y = f2tf(v1y);
            }
            *(float2*)(C + (long)r0 * ldc + col) = make_float2(v0x, v0y);
            *(float2*)(C + (long)(r0 + 8) * ldc + col) = make_float2(v1x, v1y);
        }
    }
}

// --------------------- pointwise kernels ------------------------------------
// LayerNorm over rows of 2048, vectorized loads (each thread owns 8
// consecutive elements).
__global__ void __launch_bounds__(256)
ln_rows_kernel(float* __restrict__ x, const float* __restrict__ g,
               const float* __restrict__ b)
{
    __shared__ __align__(16) float sx[G4_];
    const int tid = threadIdx.x;
    long base = (long)blockIdx.x * G4_;
    float4 v0 = *(const float4*)(x + base + tid * 8);
    float4 v1 = *(const float4*)(x + base + tid * 8 + 4);
    float s  = v0.x + v0.y + v0.z + v0.w + v1.x + v1.y + v1.z + v1.w;
    float ss = v0.x*v0.x + v0.y*v0.y + v0.z*v0.z + v0.w*v0.w
             + v1.x*v1.x + v1.y*v1.y + v1.z*v1.z + v1.w*v1.w;
    ((float4*)sx)[tid * 2]     = v0;
    ((float4*)sx)[tid * 2 + 1] = v1;
    float2 r = blockReduce2(s, ss);
    float mean = r.x * (1.0f / G4_);
    float var  = r.y * (1.0f / G4_) - mean * mean;
    float inv  = rsqrtf(var + EPS_);
    float4 g0 = *(const float4*)(g + tid * 8);
    float4 g1 = *(const float4*)(g + tid * 8 + 4);
    float4 b0 = *(const float4*)(b + tid * 8);
    float4 b1 = *(const float4*)(b + tid * 8 + 4);
    float4 o0, o1;
    o0.x = (v0.x - mean) * inv * g0.x + b0.x;
    o0.y = (v0.y - mean) * inv * g0.y + b0.y;
    o0.z = (v0.z - mean) * inv * g0.z + b0.z;
    o0.w = (v0.w - mean) * inv * g0.w + b0.w;
    o1.x = (v1.x - mean) * inv * g1.x + b1.x;
    o1.y = (v1.y - mean) * inv * g1.y + b1.y;
    o1.z = (v1.z - mean) * inv * g1.z + b1.z;
    o1.w = (v1.w - mean) * inv * g1.w + b1.w;
    *(float4*)(x + base + tid * 8)     = o0;
    *(float4*)(x + base + tid * 8 + 4) = o1;
}

__global__ void __launch_bounds__(256)
lstm_cell_kernel(const float* __restrict__ hw,
                 const float* __restrict__ gx,
                 const float* __restrict__ g_hh, const float* __restrict__ b_hh,
                 const float* __restrict__ g_c,  const float* __restrict__ b_c,
                 float* __restrict__ h, float* __restrict__ c,
                 float* __restrict__ lstm, int t)
{
    __shared__ __align__(16) float sg[G4_];
    const int b = blockIdx.x;
    const int tid = threadIdx.x;
    const float* row = hw + (long)b * G4_;
    float4 v0 = *(const float4*)(row + tid * 8);
    float4 v1 = *(const float4*)(row + tid * 8 + 4);
    float s  = v0.x + v0.y + v0.z + v0.w + v1.x + v1.y + v1.z + v1.w;
    float ss = v0.x*v0.x + v0.y*v0.y + v0.z*v0.z + v0.w*v0.w
             + v1.x*v1.x + v1.y*v1.y + v1.z*v1.z + v1.w*v1.w;
    ((float4*)sg)[tid * 2]     = v0;
    ((float4*)sg)[tid * 2 + 1] = v1;
    float2 r = blockReduce2(s, ss);
    float mean = r.x * (1.0f / G4_);
    float var  = r.y * (1.0f / G4_) - mean * mean;
    float inv  = rsqrtf(var + EPS_);

    const float* gxr = gx + ((long)b * SEQ_ + t) * G4_;
    float cval[2];
    float sc = 0.0f, ssc = 0.0f;
    #pragma unroll
    for (int rr = 0; rr < 2; rr++) {
        int j = rr * 256 + tid;
        float gi = (sg[j]        - mean) * inv * g_hh[j]        + b_hh[j]        + gxr[j];
        float gf = (sg[512 + j]  - mean) * inv * g_hh[512 + j]  + b_hh[512 + j]  + gxr[512 + j];
        float gg = (sg[1024 + j] - mean) * inv * g_hh[1024 + j] + b_hh[1024 + j] + gxr[1024 + j];
        float cn = sigm(gf) * c[(long)b * HID_ + j] + sigm(gi) * tanhf(gg);
        cval[rr] = cn;
        c[(long)b * HID_ + j] = cn;
        sc += cn; ssc += cn * cn;
    }
    float2 rc = blockReduce2(sc, ssc);
    float meanc = rc.x * (1.0f / HID_);
    float varc  = rc.y * (1.0f / HID_) - meanc * meanc;
    float invc  = rsqrtf(varc + EPS_);
    #pragma unroll
    for (int rr = 0; rr < 2; rr++) {
        int j = rr * 256 + tid;
        float go = (sg[1536 + j] - mean) * inv * g_hh[1536 + j] + b_hh[1536 + j] + gxr[1536 + j];
        float hn = sigm(go) * tanhf((cval[rr] - meanc) * invc * g_c[j] + b_c[j]);
        hn = f2tf(hn);
        h[(long)b * HID_ + j] = hn;
        lstm[((long)b * SEQ_ + t) * HID_ + j] = hn;
    }
}

// Attention: one block per batch row, all 4 heads. Scores use the identical
// 128-thread shuffle pattern per head; lstm is read ONCE per block.
__global__ void __launch_bounds__(256)
attn_kernel(const float* __restrict__ kall, const float* __restrict__ qb,
            const float* __restrict__ lstm, float* __restrict__ mbuf)
{
    const int b   = blockIdx.x;
    const int tid = threadIdx.x;
    __shared__ float se[NH_][SEQ_];
    __shared__ float wsum[SEQ_][4];
    __shared__ float ex[NH_][SEQ_];
    __shared__ float dinv[NH_];

    for (int hh = 0; hh < NH_; hh++) {
        if (tid < 128) {
            float qv = qb[(long)b * DK_ + hh * DH_ + tid];
            int w = tid >> 5, l = tid & 31;
            for (int s = 0; s < SEQ_; s++) {
                float v = kall[((long)b * SEQ_ + s) * DK_ + hh * DH_ + tid] * qv;
                #pragma unroll
                for (int o = 16; o > 0; o >>= 1)
                    v += __shfl_down_sync(0xffffffffu, v, o);
                if (l == 0) wsum[s][w] = v;
            }
        }
        __syncthreads();
        if (tid < SEQ_) {
            float sc = wsum[tid][0] + wsum[tid][1] + wsum[tid][2] + wsum[tid][3];
            se[hh][tid] = sc * 0.08838834764831845f;
        }
        __syncthreads();
    }

    if (tid < NH_) {
        float mx = -1e30f;
        #pragma unroll
        for (int s = 0; s < SEQ_; s++) mx = fmaxf(mx, se[tid][s]);
        float den = 0.0f;
        #pragma unroll
        for (int s = 0; s < SEQ_; s++) {
            float e = expf(se[tid][s] - mx);
            ex[tid][s] = e; den += e;
        }
        dinv[tid] = 1.0f / den;
    }
    __syncthreads();

    #pragma unroll
    for (int rr = 0; rr < 2; rr++) {
        int d = rr * 256 + tid;
        float a0 = 0.0f, a1 = 0.0f, a2 = 0.0f, a3 = 0.0f;
        #pragma unroll
        for (int s = 0; s < SEQ_; s++) {
            float v = lstm[((long)b * SEQ_ + s) * HID_ + d];
            a0 += ex[0][s] * v;
            a1 += ex[1][s] * v;
            a2 += ex[2][s] * v;
            a3 += ex[3][s] * v;
        }
        mbuf[((long)b * NH_ + 0) * HID_ + d] = f2tf(a0 * dinv[0]);
        mbuf[((long)b * NH_ + 1) * HID_ + d] = f2tf(a1 * dinv[1]);
        mbuf[((long)b * NH_ + 2) * HID_ + d] = f2tf(a2 * dinv[2]);
        mbuf[((long)b * NH_ + 3) * HID_ + d] = f2tf(a3 * dinv[3]);
    }
}

__global__ void __launch_bounds__(256)
out_final_kernel(const float* __restrict__ oh, const float* __restrict__ outW,
                 const float* __restrict__ outb, const float* __restrict__ label,
                 float* __restrict__ out, float* __restrict__ diff)
{
    int w = threadIdx.x >> 5, l = threadIdx.x & 31;
    int b = blockIdx.x * 8 + w;
    float s = 0.0f;
    for (int j = l; j < DK_; j += 32) s += oh[(long)b * DK_ + j] * outW[j];
    #pragma unroll
    for (int o = 16; o > 0; o >>= 1) s += __shfl_down_sync(0xffffffffu, s, o);
    if (l == 0) {
        float v = s + outb[0];
        out[1 + b] = v;
        float d = v - label[(long)b * SEQ_ + (SEQ_ - 1)];
        diff[b] = d * d;
    }
}

__global__ void __launch_bounds__(256)
loss_kernel(const float* __restrict__ diff, float* __restrict__ out)
{
    float s = 0.0f;
    for (int j = threadIdx.x; j < B_; j += 256) s += diff[j];
    float2 r = blockReduce2(s, 0.0f);
    if (threadIdx.x == 0) out[0] = r.x * (1.0f / B_);
}

// ------------------------------- launch -------------------------------------
static inline void getp(void** p, const void* sym) { cudaGetSymbolAddress(p, sym); }

extern "C" void kernel_launch(void* const* d_in, const int* in_sizes, int n_in,
                              void* d_out, int out_size)
{
    const float* visual = (const float*)d_in[0];
    const float* text   = (const float*)d_in[1];
    const float* user   = (const float*)d_in[2];
    const float* cat    = (const float*)d_in[3];
    const float* label  = (const float*)d_in[4];
    const float* h0     = (const float*)d_in[5];
    const float* c0     = (const float*)d_in[6];
    const float* fus_W  = (const float*)d_in[7];
    const float* fus_b  = (const float*)d_in[8];
    const float* W_ih   = (const float*)d_in[9];
    const float* W_hh   = (const float*)d_in[10];
    const float* g_ih   = (const float*)d_in[11];
    const float* b_ih   = (const float*)d_in[12];
    const float* g_hh   = (const float*)d_in[13];
    const float* b_hh   = (const float*)d_in[14];
    const float* g_c    = (const float*)d_in[15];
    const float* b_c    = (const float*)d_in[16];
    const float* wq_W   = (const float*)d_in[17];
    const float* wq_b   = (const float*)d_in[18];
    const float* wk_W   = (const float*)d_in[19];
    const float* wk_b   = (const float*)d_in[20];
    const float* wv_W   = (const float*)d_in[21];
    const float* wv_b   = (const float*)d_in[22];
    const float* wout_W = (const float*)d_in[23];
    const float* wout_b = (const float*)d_in[24];
    const float* out_W  = (const float*)d_in[25];
    const float* out_b  = (const float*)d_in[26];
    float* out = (float*)d_out;

    float *mods, *fusWp, *Wihp, *Whhp, *wqp, *wkp, *wvp, *woutp;
    float *vt, *gx, *hw, *h, *c, *lstm, *kall, *qb, *m, *ctx, *oh, *diff;
    getp((void**)&mods,  d_mods);  getp((void**)&fusWp, d_fusWp);
    getp((void**)&Wihp,  d_Wihp);  getp((void**)&Whhp,  d_Whhp);
    getp((void**)&wqp,   d_wqp);   getp((void**)&wkp,   d_wkp);
    getp((void**)&wvp,   d_wvp);   getp((void**)&woutp, d_woutp);
    getp((void**)&vt,    d_vt);    getp((void**)&gx,    d_gx);
    getp((void**)&hw,    d_hw);    getp((void**)&h,     d_h);
    getp((void**)&c,     d_c);     getp((void**)&lstm,  d_lstm);
    getp((void**)&kall,  d_kall);  getp((void**)&qb,    d_qb);
    getp((void**)&m,     d_m);     getp((void**)&ctx,   d_ctx);
    getp((void**)&oh,    d_oh);    getp((void**)&diff,  d_diff);

    cudaFuncSetAttribute(tgemm, cudaFuncAttributeMaxDynamicSharedMemorySize, SMEM_G);

    // 0. producers
    {
        long nthr = (long)BS_ * 4096 / 4;
        conv_concat<<<(unsigned)((nthr + 255) / 256), 256>>>(visual, text, user, cat, mods);
    }
    {
        long total = SZ_FUS + SZ_IH + SZ_HH + 2 * SZ_QK + SZ_WV + SZ_OUT;
        perm_all<<<(unsigned)((total + 255) / 256), 256>>>(
            fus_W, W_ih, W_hh, wq_W, wk_W, wv_W, wout_W,
            fusWp, Wihp, Whhp, wqp, wkp, wvp, woutp);
    }
    round_vec<<<(B_ * HID_ + 255) / 256, 256>>>(h0, h, (long)B_ * HID_);
    cudaMemcpyAsync(c, c0, (size_t)B_ * HID_ * sizeof(float), cudaMemcpyDeviceToDevice, 0);

    // 1. fusion GEMM + relu -> vt (rounded)
    tgemm<<<dim3(DIM_ / NT, BS_ / MT), 256, SMEM_G>>>(
        mods, 4096, 0, fusWp, 0, DIM_, vt, DIM_, 0, 4096, fus_b, 0, 1, 1);

    // 2. gx = vt @ W_ih^T
    tgemm<<<dim3(G4_ / NT, BS_ / MT), 256, SMEM_G>>>(
        vt, DIM_, 0, Wihp, 0, G4_, gx, G4_, 0, DIM_, (const float*)0, 0, 0, 0);

    // 3. LSTM recurrence (first GEMM before ln_rows, as in champion)
    tgemm<<<dim3(G4_ / NT, B_ / MT), 256, SMEM_G>>>(
        h, HID_, 0, Whhp, 0, G4_, hw, G4_, 0, HID_, (const float*)0, 0, 0, 0);
    ln_rows_kernel<<<BS_, 256>>>(gx, g_ih, b_ih);
    lstm_cell_kernel<<<B_, 256>>>(hw, gx, g_hh, b_hh, g_c, b_c, h, c, lstm, 0);
    for (int t = 1; t < SEQ_; t++) {
        tgemm<<<dim3(G4_ / NT, B_ / MT), 256, SMEM_G>>>(
            h, HID_, 0, Whhp, 0, G4_, hw, G4_, 0, HID_, (const float*)0, 0, 0, 0);
        lstm_cell_kernel<<<B_, 256>>>(hw, gx, g_hh, b_hh, g_c, b_c, h, c, lstm, t);
    }

    // 4. k / q projections
    tgemm<<<dim3(DK_ / NT, BS_ / MT), 256, SMEM_G>>>(
        lstm, HID_, 0, wkp, 0, DK_, kall, DK_, 0, HID_, wk_b, 0, 0, 0);
    tgemm<<<dim3(DK_ / NT, B_ / MT), 256, SMEM_G>>>(
        h, HID_, 0, wqp, 0, DK_, qb, DK_, 0, HID_, wq_b, 0, 0, 0);

    // 5. attention -> m (rounded); one block per batch row
    attn_kernel<<<B_, 256>>>(kall, qb, lstm, m);

    // 6. ctx = wv_W . m  (batched over heads, rounded)
    tgemm<<<dim3(DK_ / NT, B_ / MT, NH_), 256, SMEM_G>>>(
        m, NH_ * HID_, HID_, wvp, (long)DK_ * HID_, DK_,
        ctx, NH_ * DK_, DK_, HID_, wv_b, DK_, 0, 1);

    // 7. out_h = ctx @ wout_W^T
    tgemm<<<dim3(DK_ / NT, B_ / MT), 256, SMEM_G>>>(
        ctx, NH_ * DK_, 0, woutp, 0, DK_, oh, DK_, 0, NH_ * DK_, wout_b, 0, 0, 0);

    // 8. final projection + loss
    out_final_kernel<<<B_ / 8, 256>>>(oh, out_W, out_b, label, out, diff);
    loss_kernel<<<1, 256>>>(diff, out);
}

// round 17
// speedup vs baseline: 1.1491x; 1.0151x over previous
#include <cuda_runtime.h>
#include <math.h>

// ---------------------------------------------------------------------------
// att_lstm round 17: round-16 champion + conv_concat DELETED the right way:
// GEMM-1 (tgemm_fus2) cp.async's RAW fp32 straight from the 4 modality
// tensors (segment-uniform per BK strip) and applies cvt.rna.tf32 to the A
// fragments post-ldmatrix (bit-identical to pre-rounding; alu slots are free
// per ncu: issue 28%, alu 9%).
// ---------------------------------------------------------------------------

#define B_    2048
#define SEQ_  16
#define DIM_  1024
#define HID_  512
#define DK_   512
#define NH_   4
#define DH_   128
#define G4_   (4 * HID_)      // 2048
#define BS_   (B_ * SEQ_)     // 32768
#define EPS_  1e-5f

#define MT 128
#define NT 128
#define BK 32
#define ASTR 36
#define ABYTES (128 * ASTR * 4)       // 18432
#define BBYTES (2 * 16 * 512)         // 16384
#define STG (ABYTES + BBYTES)         // 34816
#define NSTG 3
#define SMEM_G (NSTG * STG)           // 104448

// ------------------------------- scratch -----------------------------------
__device__ float d_fusWp[4096 * DIM_];
__device__ float d_Wihp [G4_ * DIM_];
__device__ float d_Whhp [G4_ * HID_];
__device__ float d_wqp  [DK_ * HID_];
__device__ float d_wkp  [DK_ * HID_];
__device__ float d_wvp  [NH_ * DK_ * HID_];
__device__ float d_woutp[DK_ * NH_ * DK_];
__device__ float d_vt  [(long)BS_ * DIM_];
__device__ float d_gx  [(long)BS_ * G4_];
__device__ float d_hw  [B_  * G4_];
__device__ float d_h   [B_  * HID_];
__device__ float d_c   [B_  * HID_];
__device__ float d_lstm[(long)BS_ * HID_];
__device__ float d_kall[(long)BS_ * DK_];
__device__ float d_qb  [B_  * DK_];
__device__ float d_m   [B_  * NH_ * HID_];
__device__ float d_ctx [B_  * NH_ * DK_];
__device__ float d_oh  [B_  * DK_];
__device__ float d_diff[B_];

// --------------------------- helpers ---------------------------------------
__device__ __forceinline__ float sigm(float x) { return 1.0f / (1.0f + expf(-x)); }

__device__ __forceinline__ float f2tf(float f) {
    unsigned u;
    asm("cvt.rna.tf32.f32 %0, %1;" : "=r"(u) : "f"(f));
    return __uint_as_float(u);
}

__device__ __forceinline__ unsigned u2tf(unsigned x) {
    unsigned u;
    asm("cvt.rna.tf32.f32 %0, %1;" : "=r"(u) : "f"(__uint_as_float(x)));
    return u;
}

__device__ __forceinline__ void cpa16(unsigned dst, const void* src) {
    asm volatile("cp.async.cg.shared.global [%0], [%1], 16;\n" :: "r"(dst), "l"(src));
}
__device__ __forceinline__ void cpa_commit() { asm volatile("cp.async.commit_group;\n"); }
__device__ __forceinline__ void cpa_wait1()  { asm volatile("cp.async.wait_group 1;\n"); }

__device__ __forceinline__ void ldm4(unsigned* r, unsigned addr) {
    asm volatile("ldmatrix.sync.aligned.m8n8.x4.shared.b16 {%0,%1,%2,%3}, [%4];"
        : "=r"(r[0]), "=r"(r[1]), "=r"(r[2]), "=r"(r[3]) : "r"(addr));
}

__device__ __forceinline__ void lds2(unsigned& a, unsigned& b, unsigned addr) {
    asm volatile("ld.shared.v2.b32 {%0,%1}, [%2];" : "=r"(a), "=r"(b) : "r"(addr));
}

__device__ __forceinline__ void mma_tf32(float* c, const unsigned* a,
                                         unsigned b0, unsigned b1) {
    asm volatile(
        "mma.sync.aligned.m16n8k8.row.col.f32.tf32.tf32.f32 "
        "{%0,%1,%2,%3},{%4,%5,%6,%7},{%8,%9},{%0,%1,%2,%3};\n"
        : "+f"(c[0]), "+f"(c[1]), "+f"(c[2]), "+f"(c[3])
        : "r"(a[0]), "r"(a[1]), "r"(a[2]), "r"(a[3]), "r"(b0), "r"(b1));
}

__device__ __forceinline__ float2 blockReduce2(float a, float b) {
    __shared__ float s1[8], s2[8];
    const unsigned m = 0xffffffffu;
    #pragma unroll
    for (int o = 16; o > 0; o >>= 1) {
        a += __shfl_down_sync(m, a, o);
        b += __shfl_down_sync(m, b, o);
    }
    int w = threadIdx.x >> 5, l = threadIdx.x & 31;
    if (l == 0) { s1[w] = a; s2[w] = b; }
    __syncthreads();
    int nw = blockDim.x >> 5;
    if (w == 0) {
        a = (l < nw) ? s1[l] : 0.0f;
        b = (l < nw) ? s2[l] : 0.0f;
        #pragma unroll
        for (int o = 4; o > 0; o >>= 1) {
            a += __shfl_down_sync(m, a, o);
            b += __shfl_down_sync(m, b, o);
        }
        if (l == 0) { s1[0] = a; s2[0] = b; }
    }
    __syncthreads();
    float2 r = make_float2(s1[0], s2[0]);
    __syncthreads();
    return r;
}

// ------------------------ producers ----------------------------------------
#define SZ_FUS ((long)DIM_ * 4096)
#define SZ_IH  ((long)G4_ * DIM_)
#define SZ_HH  ((long)G4_ * HID_)
#define SZ_QK  ((long)DK_ * HID_)
#define SZ_WV  ((long)NH_ * DK_ * HID_)
#define SZ_OUT ((long)DK_ * NH_ * DK_)
__global__ void __launch_bounds__(256)
perm_all(const float* __restrict__ fus_W, const float* __restrict__ W_ih,
         const float* __restrict__ W_hh,  const float* __restrict__ wq_W,
         const float* __restrict__ wk_W,  const float* __restrict__ wv_W,
         const float* __restrict__ wout_W,
         float* __restrict__ fusWp, float* __restrict__ Wihp,
         float* __restrict__ Whhp,  float* __restrict__ wqp,
         float* __restrict__ wkp,   float* __restrict__ wvp,
         float* __restrict__ woutp)
{
    long i = (long)blockIdx.x * 256 + threadIdx.x;
    const long e0 = SZ_FUS, e1 = e0 + SZ_IH, e2 = e1 + SZ_HH, e3 = e2 + SZ_QK,
               e4 = e3 + SZ_QK, e5 = e4 + SZ_WV, e6 = e5 + SZ_OUT;
    if (i >= e6) return;
    const float* W; float* P; int N, K; long off;
    if (i < e0)      { W = fus_W;  P = fusWp;  N = DIM_; K = 4096;      off = i; }
    else if (i < e1) { W = W_ih;   P = Wihp;   N = G4_;  K = DIM_;      off = i - e0; }
    else if (i < e2) { W = W_hh;   P = Whhp;   N = G4_;  K = HID_;      off = i - e1; }
    else if (i < e3) { W = wq_W;   P = wqp;    N = DK_;  K = HID_;      off = i - e2; }
    else if (i < e4) { W = wk_W;   P = wkp;    N = DK_;  K = HID_;      off = i - e3; }
    else if (i < e5) {
        long o = i - e4;
        long hsz = (long)DK_ * HID_;
        int z = (int)(o / hsz);
        W = wv_W + (long)z * hsz; P = wvp + (long)z * hsz;
        N = DK_; K = HID_; off = o - (long)z * hsz;
    }
    else             { W = wout_W; P = woutp;  N = DK_;  K = NH_ * DK_; off = i - e5; }
    int k = (int)(off % K);
    int nn = (int)(off / K);
    int kg = k >> 4, nt = nn >> 3;
    int q2 = (k >> 3) & 1, pos = (k >> 2) & 1;
    int l = (nn & 7) * 4 + (k & 3);
    long o2 = ((((long)kg * (N >> 3) + nt) * 2 + q2) * 64) + l * 2 + pos;
    P[o2] = f2tf(W[off]);
}

__global__ void __launch_bounds__(256)
round_vec(const float* __restrict__ s, float* __restrict__ d, long n)
{
    long i = (long)blockIdx.x * 256 + threadIdx.x;
    if (i < n) d[i] = f2tf(s[i]);
}

// --------------------------- tf32 GEMM (champion) ----------------------------
__global__ void __launch_bounds__(256, 2)
tgemm(const float* __restrict__ A, int lda, long sAz,
      const float* __restrict__ Bp, long sBz, int N,
      float* __restrict__ C, int ldc, long sCz, int K,
      const float* __restrict__ bias, int sbz, int act, int rnd)
{
    extern __shared__ __align__(16) float dsm[];
    const int tid = threadIdx.x;
    const int m0 = blockIdx.y * MT;
    const int nt0 = blockIdx.x * 16;
    A  += (long)blockIdx.z * sAz;
    Bp += (long)blockIdx.z * sBz;
    C  += (long)blockIdx.z * sCz;
    const float* bz = bias ? bias + (long)blockIdx.z * sbz : (const float*)0;

    const int w = tid >> 5, lane = tid & 31;
    const int wm = w & 3, wn = w >> 2;
    const int gid = lane >> 2, tig = lane & 3;

    const unsigned sb = (unsigned)__cvta_generic_to_shared(dsm);
    const int NT8 = N >> 3;

    float acc[2][8][4];
    #pragma unroll
    for (int i = 0; i < 2; i++)
        #pragma unroll
        for (int j = 0; j < 8; j++)
            #pragma unroll
            for (int q = 0; q < 4; q++) acc[i][j][q] = 0.0f;

    const int KT = K / BK;

    const int ar = tid >> 3, ach = tid & 7;
    auto loadStage = [&](int stg, int k0) {
        const unsigned as = sb + (unsigned)stg * STG;
        #pragma unroll
        for (int i = 0; i < 4; i++) {
            int r = ar + i * 32;
            cpa16(as + (unsigned)(r * ASTR * 4 + ach * 16),
                  A + (long)(m0 + r) * lda + k0 + ach * 4);
        }
        const unsigned bs = as + ABYTES;
        const int kg0 = k0 >> 4;
        #pragma unroll
        for (int i = 0; i < 4; i++) {
            int g = i * 256 + tid;
            int kg2 = g >> 9, rest = g & 511;
            cpa16(bs + (unsigned)(kg2 * 8192 + rest * 16),
                  Bp + ((long)(kg0 + kg2) * NT8 + nt0) * 128 + rest * 4);
        }
    };

    loadStage(0, 0);
    cpa_commit();
    if (KT > 1) loadStage(1, BK);
    cpa_commit();

    const unsigned aoffL = (unsigned)((wm * 32 + (lane & 15)) * ASTR * 4 + (lane >> 4) * 16);
    const unsigned boffL = (unsigned)((wn * 8) * 512 + lane * 8);

    int stage = 0;
    for (int t = 0; t < KT; t++) {
        cpa_wait1();
        __syncthreads();
        const unsigned as = sb + (unsigned)stage * STG;
        const unsigned bs = as + ABYTES;
        #pragma unroll
        for (int kk = 0; kk < 4; kk++) {
            unsigned af0[4], af1[4];
            ldm4(af0, as + aoffL + kk * 32);
            ldm4(af1, as + aoffL + 16 * ASTR * 4 + kk * 32);
            const unsigned bb = bs + boffL + (kk >> 1) * 8192 + (kk & 1) * 256;
            #pragma unroll
            for (int j = 0; j < 8; j++) {
                unsigned b0, b1;
                lds2(b0, b1, bb + j * 512);
                mma_tf32(acc[0][j], af0, b0, b1);
                mma_tf32(acc[1][j], af1, b0, b1);
            }
        }
        if (t + 2 < KT) {
            int ns = stage + 2; if (ns >= NSTG) ns -= NSTG;
            loadStage(ns, (t + 2) * BK);
        }
        cpa_commit();
        if (++stage == NSTG) stage = 0;
    }

    const int n0 = nt0 * 8;
    #pragma unroll
    for (int i = 0; i < 2; i++) {
        const int r0 = m0 + wm * 32 + i * 16 + gid;
        #pragma unroll
        for (int j = 0; j < 8; j++) {
            const int col = n0 + wn * 64 + j * 8 + 2 * tig;
            float bx = 0.0f, by = 0.0f;
            if (bz) { bx = bz[col]; by = bz[col + 1]; }
            float v0x = acc[i][j][0] + bx, v0y = acc[i][j][1] + by;
            float v1x = acc[i][j][2] + bx, v1y = acc[i][j][3] + by;
            if (act) {
                v0x = fmaxf(v0x, 0.0f); v0y = fmaxf(v0y, 0.0f);
                v1x = fmaxf(v1x, 0.0f); v1y = fmaxf(v1y, 0.0f);
            }
            if (rnd) {
                v0x = f2tf(v0x); v0y = f2tf(v0y);
                v1x = f2tf(v1x); v1y = f2tf(v1y);
            }
            *(float2*)(C + (long)r0 * ldc + col) = make_float2(v0x, v0y);
            *(float2*)(C + (long)(r0 + 8) * ldc + col) = make_float2(v1x, v1y);
        }
    }
}

// ----------- GEMM-1: virtual-concat A via cp.async + post-ldmatrix cvt ------
// A raw fp32 cp.async'd from segment-selected modality tensor; cvt.rna.tf32
// applied to A fragments after ldmatrix (bit-identical to pre-rounding).
__global__ void __launch_bounds__(256, 2)
tgemm_fus2(const float* __restrict__ p0, const float* __restrict__ p1,
           const float* __restrict__ p2, const float* __restrict__ p3,
           const float* __restrict__ Bp,
           float* __restrict__ C, const float* __restrict__ bias)
{
    extern __shared__ __align__(16) float dsm[];
    const int tid = threadIdx.x;
    const int m0 = blockIdx.y * MT;
    const int nt0 = blockIdx.x * 16;
    const int K = 4096, N = DIM_;

    const int w = tid >> 5, lane = tid & 31;
    const int wm = w & 3, wn = w >> 2;
    const int gid = lane >> 2, tig = lane & 3;

    const unsigned sb = (unsigned)__cvta_generic_to_shared(dsm);
    const int NT8 = N >> 3;

    float acc[2][8][4];
    #pragma unroll
    for (int i = 0; i < 2; i++)
        #pragma unroll
        for (int j = 0; j < 8; j++)
            #pragma unroll
            for (int q = 0; q < 4; q++) acc[i][j][q] = 0.0f;

    const int KT = K / BK;     // 128

    const int ar = tid >> 3, ach = tid & 7;
    auto loadStage = [&](int stg, int k0) {
        // segment-uniform per stage: BK=32 strip never crosses 1024 boundary
        const int seg = k0 >> 10, kl = k0 & 1023;
        const float* p = (seg == 0) ? p0 : (seg == 1) ? p1 : (seg == 2) ? p2 : p3;
        const unsigned as = sb + (unsigned)stg * STG;
        #pragma unroll
        for (int i = 0; i < 4; i++) {
            int r = ar + i * 32;
            cpa16(as + (unsigned)(r * ASTR * 4 + ach * 16),
                  p + (long)(m0 + r) * DIM_ + kl + ach * 4);
        }
        const unsigned bs = as + ABYTES;
        const int kg0 = k0 >> 4;
        #pragma unroll
        for (int i = 0; i < 4; i++) {
            int g = i * 256 + tid;
            int kg2 = g >> 9, rest = g & 511;
            cpa16(bs + (unsigned)(kg2 * 8192 + rest * 16),
                  Bp + ((long)(kg0 + kg2) * NT8 + nt0) * 128 + rest * 4);
        }
    };

    loadStage(0, 0);
    cpa_commit();
    loadStage(1, BK);
    cpa_commit();

    const unsigned aoffL = (unsigned)((wm * 32 + (lane & 15)) * ASTR * 4 + (lane >> 4) * 16);
    const unsigned boffL = (unsigned)((wn * 8) * 512 + lane * 8);

    int stage = 0;
    for (int t = 0; t < KT; t++) {
        cpa_wait1();
        __syncthreads();
        const unsigned as = sb + (unsigned)stage * STG;
        const unsigned bs = as + ABYTES;
        #pragma unroll
        for (int kk = 0; kk < 4; kk++) {
            unsigned af0[4], af1[4];
            ldm4(af0, as + aoffL + kk * 32);
            ldm4(af1, as + aoffL + 16 * ASTR * 4 + kk * 32);
            #pragma unroll
            for (int q = 0; q < 4; q++) { af0[q] = u2tf(af0[q]); af1[q] = u2tf(af1[q]); }
            const unsigned bb = bs + boffL + (kk >> 1) * 8192 + (kk & 1) * 256;
            #pragma unroll
            for (int j = 0; j < 8; j++) {
                unsigned b0, b1;
                lds2(b0, b1, bb + j * 512);
                mma_tf32(acc[0][j], af0, b0, b1);
                mma_tf32(acc[1][j], af1, b0, b1);
            }
        }
        if (t + 2 < KT) {
            int ns = stage + 2; if (ns >= NSTG) ns -= NSTG;
            loadStage(ns, (t + 2) * BK);
        }
        cpa_commit();
        if (++stage == NSTG) stage = 0;
    }

    const int n0 = nt0 * 8;
    #pragma unroll
    for (int i = 0; i < 2; i++) {
        const int r0 = m0 + wm * 32 + i * 16 + gid;
        #pragma unroll
        for (int j = 0; j < 8; j++) {
            const int col = n0 + wn * 64 + j * 8 + 2 * tig;
            float bx = bias[col], by = bias[col + 1];
            float v0x = f2tf(fmaxf(acc[i][j][0] + bx, 0.0f));
            float v0y = f2tf(fmaxf(acc[i][j][1] + by, 0.0f));
            float v1x = f2tf(fmaxf(acc[i][j][2] + bx, 0.0f));
            float v1y = f2tf(fmaxf(acc[i][j][3] + by, 0.0f));
            *(float2*)(C + (long)r0 * DIM_ + col) = make_float2(v0x, v0y);
            *(float2*)(C + (long)(r0 + 8) * DIM_ + col) = make_float2(v1x, v1y);
        }
    }
}

// --------------------- pointwise kernels (round-16) --------------------------
__global__ void __launch_bounds__(256)
ln_rows_kernel(float* __restrict__ x, const float* __restrict__ g,
               const float* __restrict__ b)
{
    __shared__ __align__(16) float sx[G4_];
    const int tid = threadIdx.x;
    long base = (long)blockIdx.x * G4_;
    float4 v0 = *(const float4*)(x + base + tid * 8);
    float4 v1 = *(const float4*)(x + base + tid * 8 + 4);
    float s  = v0.x + v0.y + v0.z + v0.w + v1.x + v1.y + v1.z + v1.w;
    float ss = v0.x*v0.x + v0.y*v0.y + v0.z*v0.z + v0.w*v0.w
             + v1.x*v1.x + v1.y*v1.y + v1.z*v1.z + v1.w*v1.w;
    ((float4*)sx)[tid * 2]     = v0;
    ((float4*)sx)[tid * 2 + 1] = v1;
    float2 r = blockReduce2(s, ss);
    float mean = r.x * (1.0f / G4_);
    float var  = r.y * (1.0f / G4_) - mean * mean;
    float inv  = rsqrtf(var + EPS_);
    float4 g0 = *(const float4*)(g + tid * 8);
    float4 g1 = *(const float4*)(g + tid * 8 + 4);
    float4 b0 = *(const float4*)(b + tid * 8);
    float4 b1 = *(const float4*)(b + tid * 8 + 4);
    float4 o0, o1;
    o0.x = (v0.x - mean) * inv * g0.x + b0.x;
    o0.y = (v0.y - mean) * inv * g0.y + b0.y;
    o0.z = (v0.z - mean) * inv * g0.z + b0.z;
    o0.w = (v0.w - mean) * inv * g0.w + b0.w;
    o1.x = (v1.x - mean) * inv * g1.x + b1.x;
    o1.y = (v1.y - mean) * inv * g1.y + b1.y;
    o1.z = (v1.z - mean) * inv * g1.z + b1.z;
    o1.w = (v1.w - mean) * inv * g1.w + b1.w;
    *(float4*)(x + base + tid * 8)     = o0;
    *(float4*)(x + base + tid * 8 + 4) = o1;
}

__global__ void __launch_bounds__(256)
lstm_cell_kernel(const float* __restrict__ hw,
                 const float* __restrict__ gx,
                 const float* __restrict__ g_hh, const float* __restrict__ b_hh,
                 const float* __restrict__ g_c,  const float* __restrict__ b_c,
                 float* __restrict__ h, float* __restrict__ c,
                 float* __restrict__ lstm, int t)
{
    __shared__ __align__(16) float sg[G4_];
    const int b = blockIdx.x;
    const int tid = threadIdx.x;
    const float* row = hw + (long)b * G4_;
    float4 v0 = *(const float4*)(row + tid * 8);
    float4 v1 = *(const float4*)(row + tid * 8 + 4);
    float s  = v0.x + v0.y + v0.z + v0.w + v1.x + v1.y + v1.z + v1.w;
    float ss = v0.x*v0.x + v0.y*v0.y + v0.z*v0.z + v0.w*v0.w
             + v1.x*v1.x + v1.y*v1.y + v1.z*v1.z + v1.w*v1.w;
    ((float4*)sg)[tid * 2]     = v0;
    ((float4*)sg)[tid * 2 + 1] = v1;
    float2 r = blockReduce2(s, ss);
    float mean = r.x * (1.0f / G4_);
    float var  = r.y * (1.0f / G4_) - mean * mean;
    float inv  = rsqrtf(var + EPS_);

    const float* gxr = gx + ((long)b * SEQ_ + t) * G4_;
    float cval[2];
    float sc = 0.0f, ssc = 0.0f;
    #pragma unroll
    for (int rr = 0; rr < 2; rr++) {
        int j = rr * 256 + tid;
        float gi = (sg[j]        - mean) * inv * g_hh[j]        + b_hh[j]        + gxr[j];
        float gf = (sg[512 + j]  - mean) * inv * g_hh[512 + j]  + b_hh[512 + j]  + gxr[512 + j];
        float gg = (sg[1024 + j] - mean) * inv * g_hh[1024 + j] + b_hh[1024 + j] + gxr[1024 + j];
        float cn = sigm(gf) * c[(long)b * HID_ + j] + sigm(gi) * tanhf(gg);
        cval[rr] = cn;
        c[(long)b * HID_ + j] = cn;
        sc += cn; ssc += cn * cn;
    }
    float2 rc = blockReduce2(sc, ssc);
    float meanc = rc.x * (1.0f / HID_);
    float varc  = rc.y * (1.0f / HID_) - meanc * meanc;
    float invc  = rsqrtf(varc + EPS_);
    #pragma unroll
    for (int rr = 0; rr < 2; rr++) {
        int j = rr * 256 + tid;
        float go = (sg[1536 + j] - mean) * inv * g_hh[1536 + j] + b_hh[1536 + j] + gxr[1536 + j];
        float hn = sigm(go) * tanhf((cval[rr] - meanc) * invc * g_c[j] + b_c[j]);
        hn = f2tf(hn);
        h[(long)b * HID_ + j] = hn;
        lstm[((long)b * SEQ_ + t) * HID_ + j] = hn;
    }
}

__global__ void __launch_bounds__(256)
attn_kernel(const float* __restrict__ kall, const float* __restrict__ qb,
            const float* __restrict__ lstm, float* __restrict__ mbuf)
{
    const int b   = blockIdx.x;
    const int tid = threadIdx.x;
    __shared__ float se[NH_][SEQ_];
    __shared__ float wsum[SEQ_][4];
    __shared__ float ex[NH_][SEQ_];
    __shared__ float dinv[NH_];

    for (int hh = 0; hh < NH_; hh++) {
        if (tid < 128) {
            float qv = qb[(long)b * DK_ + hh * DH_ + tid];
            int w = tid >> 5, l = tid & 31;
            for (int s = 0; s < SEQ_; s++) {
                float v = kall[((long)b * SEQ_ + s) * DK_ + hh * DH_ + tid] * qv;
                #pragma unroll
                for (int o = 16; o > 0; o >>= 1)
                    v += __shfl_down_sync(0xffffffffu, v, o);
                if (l == 0) wsum[s][w] = v;
            }
        }
        __syncthreads();
        if (tid < SEQ_) {
            float sc = wsum[tid][0] + wsum[tid][1] + wsum[tid][2] + wsum[tid][3];
            se[hh][tid] = sc * 0.08838834764831845f;
        }
        __syncthreads();
    }

    if (tid < NH_) {
        float mx = -1e30f;
        #pragma unroll
        for (int s = 0; s < SEQ_; s++) mx = fmaxf(mx, se[tid][s]);
        float den = 0.0f;
        #pragma unroll
        for (int s = 0; s < SEQ_; s++) {
            float e = expf(se[tid][s] - mx);
            ex[tid][s] = e; den += e;
        }
        dinv[tid] = 1.0f / den;
    }
    __syncthreads();

    #pragma unroll
    for (int rr = 0; rr < 2; rr++) {
        int d = rr * 256 + tid;
        float a0 = 0.0f, a1 = 0.0f, a2 = 0.0f, a3 = 0.0f;
        #pragma unroll
        for (int s = 0; s < SEQ_; s++) {
            float v = lstm[((long)b * SEQ_ + s) * HID_ + d];
            a0 += ex[0][s] * v;
            a1 += ex[1][s] * v;
            a2 += ex[2][s] * v;
            a3 += ex[3][s] * v;
        }
        mbuf[((long)b * NH_ + 0) * HID_ + d] = f2tf(a0 * dinv[0]);
        mbuf[((long)b * NH_ + 1) * HID_ + d] = f2tf(a1 * dinv[1]);
        mbuf[((long)b * NH_ + 2) * HID_ + d] = f2tf(a2 * dinv[2]);
        mbuf[((long)b * NH_ + 3) * HID_ + d] = f2tf(a3 * dinv[3]);
    }
}

__global__ void __launch_bounds__(256)
out_final_kernel(const float* __restrict__ oh, const float* __restrict__ outW,
                 const float* __restrict__ outb, const float* __restrict__ label,
                 float* __restrict__ out, float* __restrict__ diff)
{
    int w = threadIdx.x >> 5, l = threadIdx.x & 31;
    int b = blockIdx.x * 8 + w;
    float s = 0.0f;
    for (int j = l; j < DK_; j += 32) s += oh[(long)b * DK_ + j] * outW[j];
    #pragma unroll
    for (int o = 16; o > 0; o >>= 1) s += __shfl_down_sync(0xffffffffu, s, o);
    if (l == 0) {
        float v = s + outb[0];
        out[1 + b] = v;
        float d = v - label[(long)b * SEQ_ + (SEQ_ - 1)];
        diff[b] = d * d;
    }
}

__global__ void __launch_bounds__(256)
loss_kernel(const float* __restrict__ diff, float* __restrict__ out)
{
    float s = 0.0f;
    for (int j = threadIdx.x; j < B_; j += 256) s += diff[j];
    float2 r = blockReduce2(s, 0.0f);
    if (threadIdx.x == 0) out[0] = r.x * (1.0f / B_);
}

// ------------------------------- launch -------------------------------------
static inline void getp(void** p, const void* sym) { cudaGetSymbolAddress(p, sym); }

extern "C" void kernel_launch(void* const* d_in, const int* in_sizes, int n_in,
                              void* d_out, int out_size)
{
    const float* visual = (const float*)d_in[0];
    const float* text   = (const float*)d_in[1];
    const float* user   = (const float*)d_in[2];
    const float* cat    = (const float*)d_in[3];
    const float* label  = (const float*)d_in[4];
    const float* h0     = (const float*)d_in[5];
    const float* c0     = (const float*)d_in[6];
    const float* fus_W  = (const float*)d_in[7];
    const float* fus_b  = (const float*)d_in[8];
    const float* W_ih   = (const float*)d_in[9];
    const float* W_hh   = (const float*)d_in[10];
    const float* g_ih   = (const float*)d_in[11];
    const float* b_ih   = (const float*)d_in[12];
    const float* g_hh   = (const float*)d_in[13];
    const float* b_hh   = (const float*)d_in[14];
    const float* g_c    = (const float*)d_in[15];
    const float* b_c    = (const float*)d_in[16];
    const float* wq_W   = (const float*)d_in[17];
    const float* wq_b   = (const float*)d_in[18];
    const float* wk_W   = (const float*)d_in[19];
    const float* wk_b   = (const float*)d_in[20];
    const float* wv_W   = (const float*)d_in[21];
    const float* wv_b   = (const float*)d_in[22];
    const float* wout_W = (const float*)d_in[23];
    const float* wout_b = (const float*)d_in[24];
    const float* out_W  = (const float*)d_in[25];
    const float* out_b  = (const float*)d_in[26];
    float* out = (float*)d_out;

    float *fusWp, *Wihp, *Whhp, *wqp, *wkp, *wvp, *woutp;
    float *vt, *gx, *hw, *h, *c, *lstm, *kall, *qb, *m, *ctx, *oh, *diff;
    getp((void**)&fusWp, d_fusWp);
    getp((void**)&Wihp,  d_Wihp);  getp((void**)&Whhp,  d_Whhp);
    getp((void**)&wqp,   d_wqp);   getp((void**)&wkp,   d_wkp);
    getp((void**)&wvp,   d_wvp);   getp((void**)&woutp, d_woutp);
    getp((void**)&vt,    d_vt);    getp((void**)&gx,    d_gx);
    getp((void**)&hw,    d_hw);    getp((void**)&h,     d_h);
    getp((void**)&c,     d_c);     getp((void**)&lstm,  d_lstm);
    getp((void**)&kall,  d_kall);  getp((void**)&qb,    d_qb);
    getp((void**)&m,     d_m);     getp((void**)&ctx,   d_ctx);
    getp((void**)&oh,    d_oh);    getp((void**)&diff,  d_diff);

    cudaFuncSetAttribute(tgemm, cudaFuncAttributeMaxDynamicSharedMemorySize, SMEM_G);
    cudaFuncSetAttribute(tgemm_fus2, cudaFuncAttributeMaxDynamicSharedMemorySize, SMEM_G);

    // 0. producers (no conv_concat pass)
    {
        long total = SZ_FUS + SZ_IH + SZ_HH + 2 * SZ_QK + SZ_WV + SZ_OUT;
        perm_all<<<(unsigned)((total + 255) / 256), 256>>>(
            fus_W, W_ih, W_hh, wq_W, wk_W, wv_W, wout_W,
            fusWp, Wihp, Whhp, wqp, wkp, wvp, woutp);
    }
    round_vec<<<(B_ * HID_ + 255) / 256, 256>>>(h0, h, (long)B_ * HID_);
    cudaMemcpyAsync(c, c0, (size_t)B_ * HID_ * sizeof(float), cudaMemcpyDeviceToDevice, 0);

    // 1. fusion GEMM + relu -> vt; A = virtual concat via cp.async + in-frag cvt
    tgemm_fus2<<<dim3(DIM_ / NT, BS_ / MT), 256, SMEM_G>>>(
        visual, text, user, cat, fusWp, vt, fus_b);

    // 2. gx = vt @ W_ih^T
    tgemm<<<dim3(G4_ / NT, BS_ / MT), 256, SMEM_G>>>(
        vt, DIM_, 0, Wihp, 0, G4_, gx, G4_, 0, DIM_, (const float*)0, 0, 0, 0);

    // 3. LSTM recurrence (first GEMM before ln_rows)
    tgemm<<<dim3(G4_ / NT, B_ / MT), 256, SMEM_G>>>(
        h, HID_, 0, Whhp, 0, G4_, hw, G4_, 0, HID_, (const float*)0, 0, 0, 0);
    ln_rows_kernel<<<BS_, 256>>>(gx, g_ih, b_ih);
    lstm_cell_kernel<<<B_, 256>>>(hw, gx, g_hh, b_hh, g_c, b_c, h, c, lstm, 0);
    for (int t = 1; t < SEQ_; t++) {
        tgemm<<<dim3(G4_ / NT, B_ / MT), 256, SMEM_G>>>(
            h, HID_, 0, Whhp, 0, G4_, hw, G4_, 0, HID_, (const float*)0, 0, 0, 0);
        lstm_cell_kernel<<<B_, 256>>>(hw, gx, g_hh, b_hh, g_c, b_c, h, c, lstm, t);
    }

    // 4. k / q projections
    tgemm<<<dim3(DK_ / NT, BS_ / MT), 256, SMEM_G>>>(
        lstm, HID_, 0, wkp, 0, DK_, kall, DK_, 0, HID_, wk_b, 0, 0, 0);
    tgemm<<<dim3(DK_ / NT, B_ / MT), 256, SMEM_G>>>(
        h, HID_, 0, wqp, 0, DK_, qb, DK_, 0, HID_, wq_b, 0, 0, 0);

    // 5. attention -> m (rounded); one block per batch row
    attn_kernel<<<B_, 256>>>(kall, qb, lstm, m);

    // 6. ctx = wv_W . m  (batched over heads, rounded)
    tgemm<<<dim3(DK_ / NT, B_ / MT, NH_), 256, SMEM_G>>>(
        m, NH_ * HID_, HID_, wvp, (long)DK_ * HID_, DK_,
        ctx, NH_ * DK_, DK_, HID_, wv_b, DK_, 0, 1);

    // 7. out_h = ctx @ wout_W^T
    tgemm<<<dim3(DK_ / NT, B_ / MT), 256, SMEM_G>>>(
        ctx, NH_ * DK_, 0, woutp, 0, DK_, oh, DK_, 0, NH_ * DK_, wout_b, 0, 0, 0);

    // 8. final projection + loss
    out_final_kernel<<<B_ / 8, 256>>>(oh, out_W, out_b, label, out, diff);
    loss_kernel<<<1, 256>>>(diff, out);
}